// round 7
// baseline (speedup 1.0000x reference)
#include <cuda_runtime.h>
#include <cuda_bf16.h>

// ---------------------------------------------------------------------------
// FocalLoss + ArcFace, B x C (4096 x 32768 f32), targets int32, scalar f32 out.
//
// Persistent CTAs (grid = #SMs, 1 CTA/SM, 512 threads) with DOUBLE-BUFFERED
// bf16 row staging (2 x C bf16 = 131KB smem). The fused per-row loop computes
// sum(exp(k*x)) of the current row from SMEM while prefetching the next row
// from HBM (front-batched LDG.128, fp32x2 sum-of-squares, bf16 convert+STS).
// This keeps the HBM request stream continuous -> removes the phase-correlated
// idle that capped R6 at 73.6% DRAM duty. |logit| <= 30 so no max-subtract.
// Scalar f32 ex2.approx for accuracy (compute pipes are far from binding).
// Target column fixed up in exact fp32. Last CTA (ticket) writes the mean.
// ---------------------------------------------------------------------------

#define ROW_THREADS 512
#define MAX_B 16384
#define LOG2E 1.4426950408889634f

__device__ float g_rowloss[MAX_B];
__device__ unsigned int g_ticket = 0;

__device__ __forceinline__ float fast_ex2(float x) {
    float r; asm("ex2.approx.ftz.f32 %0, %1;" : "=f"(r) : "f"(x)); return r;
}
// packed acc += v*v (two fp32 lanes)
__device__ __forceinline__ void ffma2_sq(unsigned long long& acc, unsigned long long v) {
    asm("fma.rn.f32x2 %0, %1, %1, %0;" : "+l"(acc) : "l"(v));
}
__device__ __forceinline__ unsigned long long pack2(float lo, float hi) {
    unsigned long long d; asm("mov.b64 %0, {%1, %2};" : "=l"(d) : "f"(lo), "f"(hi)); return d;
}
__device__ __forceinline__ float unpack_sum(unsigned long long a) {
    float lo, hi; asm("mov.b64 {%0, %1}, %2;" : "=f"(lo), "=f"(hi) : "l"(a)); return lo + hi;
}
__device__ __forceinline__ unsigned cvt_bf2(float a, float b) {
    __nv_bfloat162 t = __floats2bfloat162_rn(a, b);
    return *reinterpret_cast<unsigned*>(&t);
}
// sum of 8 exps exp2(k*x) from a uint4 of bf16
__device__ __forceinline__ float exp8(uint4 p, float k) {
    __nv_bfloat162 b0 = *reinterpret_cast<__nv_bfloat162*>(&p.x);
    __nv_bfloat162 b1 = *reinterpret_cast<__nv_bfloat162*>(&p.y);
    __nv_bfloat162 b2 = *reinterpret_cast<__nv_bfloat162*>(&p.z);
    __nv_bfloat162 b3 = *reinterpret_cast<__nv_bfloat162*>(&p.w);
    float2 f0 = __bfloat1622float2(b0), f1 = __bfloat1622float2(b1);
    float2 f2 = __bfloat1622float2(b2), f3 = __bfloat1622float2(b3);
    float s0 = fast_ex2(f0.x * k) + fast_ex2(f0.y * k);
    float s1 = fast_ex2(f1.x * k) + fast_ex2(f1.y * k);
    float s2 = fast_ex2(f2.x * k) + fast_ex2(f2.y * k);
    float s3 = fast_ex2(f3.x * k) + fast_ex2(f3.y * k);
    return (s0 + s1) + (s2 + s3);
}

// Block-wide sum of a float2 (both components). Internal syncs publish prior
// SMEM writes; trailing sync allows `red` reuse across calls.
__device__ __forceinline__ float2 block_reduce2(float2 v, float2* red, int tid) {
    #pragma unroll
    for (int o = 16; o > 0; o >>= 1) {
        v.x += __shfl_xor_sync(0xffffffffu, v.x, o);
        v.y += __shfl_xor_sync(0xffffffffu, v.y, o);
    }
    const int warp = tid >> 5, lane = tid & 31;
    if (lane == 0) red[warp] = v;
    __syncthreads();
    if (warp == 0) {
        v = (lane < (ROW_THREADS / 32)) ? red[lane] : make_float2(0.f, 0.f);
        #pragma unroll
        for (int o = 16; o > 0; o >>= 1) {
            v.x += __shfl_xor_sync(0xffffffffu, v.x, o);
            v.y += __shfl_xor_sync(0xffffffffu, v.y, o);
        }
        if (lane == 0) red[0] = v;
    }
    __syncthreads();
    float2 r = red[0];
    __syncthreads();
    return r;
}

__global__ __launch_bounds__(ROW_THREADS, 1)
void focal_arcface_persist_kernel(const float* __restrict__ x,
                                  const int* __restrict__ tgt,
                                  int B, int C, float* __restrict__ out) {
    extern __shared__ __nv_bfloat16 sm[];          // 2*C bf16
    __shared__ float2 red[ROW_THREADS / 32];
    __shared__ unsigned is_last;

    const int tid = threadIdx.x;
    const int bid = blockIdx.x;
    const int G   = gridDim.x;
    const int n8  = C >> 3;                        // uint4 (8 bf16) per row
    const int nrows = (B - bid + G - 1) / G;       // rows: bid, bid+G, ...

    __nv_bfloat16* bufA = sm;
    __nv_bfloat16* bufB = sm + C;

    // ---- Prologue: stage first row into bufA, sum-of-squares ----
    float k;
    {
        const float4* xr = reinterpret_cast<const float4*>(x + (size_t)bid * (size_t)C);
        uint4* dA = reinterpret_cast<uint4*>(bufA);
        unsigned long long a0 = 0ull, a1 = 0ull, a2 = 0ull, a3 = 0ull;
        #pragma unroll 4
        for (int j = tid; j < n8; j += ROW_THREADS) {
            float4 v0 = xr[2 * j];
            float4 v1 = xr[2 * j + 1];
            ffma2_sq(a0, pack2(v0.x, v0.y));
            ffma2_sq(a1, pack2(v0.z, v0.w));
            ffma2_sq(a2, pack2(v1.x, v1.y));
            ffma2_sq(a3, pack2(v1.z, v1.w));
            uint4 q;
            q.x = cvt_bf2(v0.x, v0.y); q.y = cvt_bf2(v0.z, v0.w);
            q.z = cvt_bf2(v1.x, v1.y); q.w = cvt_bf2(v1.z, v1.w);
            dA[j] = q;
        }
        float ss = (unpack_sum(a0) + unpack_sum(a1)) + (unpack_sum(a2) + unpack_sum(a3));
        float2 rr = block_reduce2(make_float2(0.0f, ss), red, tid);   // publishes bufA
        float norm = fmaxf(sqrtf(rr.y), 1e-12f);
        k = (30.0f / norm) * LOG2E;                 // exp(s*x) == exp2(k*x)
    }

    // ---- Main loop: exp(row i) from SMEM while prefetching row i+1 ----
    for (int i = 0; i < nrows; i++) {
        const int r = bid + i * G;
        __nv_bfloat16* cur = (i & 1) ? bufB : bufA;
        __nv_bfloat16* nxt = (i & 1) ? bufA : bufB;
        const uint4* cur4 = reinterpret_cast<const uint4*>(cur);
        uint4* nxt4 = reinterpret_cast<uint4*>(nxt);

        // Thread 0 fetches epilogue inputs at row start (latency hidden under
        // the whole fused loop; also avoids racing buffer reuse on cur[t]).
        int t = 0; float xt = 0.0f, xtb = 0.0f;
        if (tid == 0) {
            t = tgt[r];
            t = (t < 0) ? 0 : (t >= C ? C - 1 : t);
            xt  = x[(size_t)r * (size_t)C + (size_t)t];      // exact fp32
            xtb = __bfloat162float(cur[t]);                  // what exp-sum used
        }

        float se = 0.0f, ssn = 0.0f;
        if (i + 1 < nrows) {
            const float4* xn =
                reinterpret_cast<const float4*>(x + (size_t)(r + G) * (size_t)C);
            unsigned long long a0 = 0ull, a1 = 0ull, a2 = 0ull, a3 = 0ull;
            #pragma unroll 4
            for (int j = tid; j < n8; j += ROW_THREADS) {
                float4 v0 = xn[2 * j];                 // prefetch next row
                float4 v1 = xn[2 * j + 1];
                se += exp8(cur4[j], k);                // compute hides LDG latency
                ffma2_sq(a0, pack2(v0.x, v0.y));
                ffma2_sq(a1, pack2(v0.z, v0.w));
                ffma2_sq(a2, pack2(v1.x, v1.y));
                ffma2_sq(a3, pack2(v1.z, v1.w));
                uint4 q;
                q.x = cvt_bf2(v0.x, v0.y); q.y = cvt_bf2(v0.z, v0.w);
                q.z = cvt_bf2(v1.x, v1.y); q.w = cvt_bf2(v1.z, v1.w);
                nxt4[j] = q;
            }
            ssn = (unpack_sum(a0) + unpack_sum(a1)) + (unpack_sum(a2) + unpack_sum(a3));
        } else {
            #pragma unroll 4
            for (int j = tid; j < n8; j += ROW_THREADS) {
                se += exp8(cur4[j], k);
            }
        }

        float2 rr = block_reduce2(make_float2(se, ssn), red, tid);   // publishes nxt

        if (tid == 0) {
            // cos(theta) at target, clipped like the reference
            float norm = (30.0f * LOG2E) / k;        // recover current row norm
            float c = xt / norm;
            c = fminf(fmaxf(c, -1.0f + 1e-7f), 1.0f - 1e-7f);
            const float cosM = 0.95533648912560601964f;  // cos(0.3)
            const float sinM = 0.29552020666133957511f;  // sin(0.3)
            float cosm = c * cosM - sqrtf(fmaxf(1.0f - c * c, 0.0f)) * sinM;
            float lt = 30.0f * cosm;                 // target logit

            float sum = rr.x - fast_ex2(xtb * k) + expf(lt);
            float lse = logf(sum);                   // |logit|<=30: no max needed
            float ce  = lse - lt;
            float pt  = expf(-ce);
            float om  = 1.0f - pt;
            g_rowloss[r] = om * om * ce;             // gamma = 2
        }

        float normn = fmaxf(sqrtf(rr.y), 1e-12f);    // next row's norm
        k = (30.0f / normn) * LOG2E;
    }

    // ---- Ticketed final reduce (last CTA computes the mean) ----
    if (tid == 0) {
        __threadfence();                             // release rowloss writes
        unsigned done = atomicAdd(&g_ticket, 1u);
        is_last = (done == (unsigned)G - 1u) ? 1u : 0u;
        if (is_last) __threadfence();                // acquire others' writes
    }
    __syncthreads();

    if (is_last) {
        float v = 0.0f;
        for (int i = tid; i < B; i += ROW_THREADS) v += __ldcg(&g_rowloss[i]);
        float2 rr = block_reduce2(make_float2(v, 0.0f), red, tid);
        if (tid == 0) {
            out[0] = rr.x / (float)B;
            g_ticket = 0;                            // reset for next graph replay
        }
    }
}

extern "C" void kernel_launch(void* const* d_in, const int* in_sizes, int n_in,
                              void* d_out, int out_size) {
    // Identify slots by size: big buffer = inputs, small = targets.
    int xi = 0, ti = 1;
    if (n_in >= 2 && in_sizes[1] > in_sizes[0]) { xi = 1; ti = 0; }

    const float* x   = (const float*)d_in[xi];
    const int*   tgt = (const int*)d_in[ti];     // int64 lowered to i32 by harness

    const int B = in_sizes[ti];
    const int C = in_sizes[xi] / B;

    static int sms = 0;                          // cached; host-side query, capture-safe
    if (sms == 0) {
        cudaDeviceGetAttribute(&sms, cudaDevAttrMultiProcessorCount, 0);
        if (sms <= 0) sms = 148;
    }
    int grid = (B < sms) ? B : sms;

    const size_t smem = 2 * (size_t)C * sizeof(__nv_bfloat16);  // 131KB for C=32768
    cudaFuncSetAttribute(focal_arcface_persist_kernel,
                         cudaFuncAttributeMaxDynamicSharedMemorySize,
                         (int)smem);

    focal_arcface_persist_kernel<<<grid, ROW_THREADS, smem>>>(x, tgt, B, C,
                                                              (float*)d_out);
}